// round 15
// baseline (speedup 1.0000x reference)
#include <cuda_runtime.h>
#include <cuda_fp16.h>
#include <cstdint>
#include <cstddef>

// Problem constants
#define TT 20
#define BB 1024
#define DD 2312
#define D4 578            // DD / 4, exact

// Persistent kernel: 147 blocks x 896 threads, 1 block/SM (~74.5KB smem).
// Blocks 0..145 own 7 rows each; block 146 owns rows 1022..1023.
#define NBLK 147
#define NTHR 896
#define GSZ  128          // threads per row-group
#define NGRP 7            // max rows per block
#define NS4  5            // ceil(578/128) float4 slots per thread
#define TAIL4 66          // 578 - 4*128

#define L2E 1.4426950408889634f

// ---- Arrive-first grid barrier ----
// g_cnt2[p]: arrival counter for barriers of parity p. Reset by the releaser
//   of barrier k (parity k&1) BEFORE its release is visible; arrivals at k+2
//   (same parity) require having observed release(k) -> no race. Both
//   counters are 0 at launch end (releases TT-2, TT-1 reset them last).
// g_rel2[p] = ((k+1) << 32) | float_bits(bs(k)) for the latest released
//   barrier k of parity p. Consumers EQUALITY-spin on high == t+1:
//   - no deadlock: release(t+2) can't overwrite parity word t&1 before every
//     block observed release(t), because arrivals at t+2 are program-ordered
//     after that block's observation of release(t);
//   - no stale-match: per-block, spins on one parity word see a monotone
//     value sequence (1,3,..,19 / 2,4,..,20), each value observed before the
//     next can be published; cross-launch leftovers (19/20) never equal the
//     first wanted values (1/2). No init zeroing needed; end-state is
//     identical every launch -> graph replays are deterministic.
// g_bsum[k]: per-step accumulator; slot (k+TT-1)%TT cleaned at release k
//   (one-late clean, quiescent: consumed only by releaser of k-1).
__device__ unsigned           g_cnt2[2];
__device__ float              g_bsum[TT];
__device__ unsigned long long g_rel2[2];

__device__ __forceinline__ float warp_sum(float v) {
#pragma unroll
    for (int o = 16; o > 0; o >>= 1)
        v += __shfl_xor_sync(0xffffffffu, v, o);
    return v;
}

__device__ __forceinline__ float ex2a(float x) {
    float y; asm("ex2.approx.ftz.f32 %0, %1;" : "=f"(y) : "f"(x)); return y;
}
__device__ __forceinline__ float rcpa(float x) {
    float y; asm("rcp.approx.ftz.f32 %0, %1;" : "=f"(y) : "f"(x)); return y;
}
__device__ __forceinline__ float tanha(float x) {
    float y; asm("tanh.approx.f32 %0, %1;" : "=f"(y) : "f"(x)); return y;
}
// exact-path sigmoid (2 MUFU) — used only in one-time init
__device__ __forceinline__ float sigm(float x) {
    return rcpa(1.0f + ex2a(-x * L2E));
}

__global__ void __launch_bounds__(NTHR, 1)
snn_etad_kernel(const float* __restrict__ x,
                const float* __restrict__ ac,
                const float* __restrict__ tw,
                const float* __restrict__ ig,
                const float* __restrict__ p_md,
                const float* __restrict__ p_sd,
                const float* __restrict__ p_th,
                float* __restrict__ out)
{
    extern __shared__ char smraw[];
    // c ping-pong: [2][NGRP][D4*2] half2 (fp16 compressed values)
    __half2* s_c  = (__half2*)smraw;                    // 2*7*1156 half2
    __half2* s_ag = s_c + 2 * NGRP * D4 * 2;            // DD half2 {0.5*a, g}
    float*   s_rS = (float*)(s_ag + DD);                // 32
    float*   s_rW = s_rS + 32;                          // 32
    float*   s_rA = s_rW + 32;                          // 2 x 32 ping-pong
    float*   s_bsv = s_rA + 64;                         // 1
    volatile int* s_step = (volatile int*)(s_bsv + 1);  // 1

    const int tid  = threadIdx.x;
    const int grp  = tid >> 7;         // 0..6 row-group
    const int gtid = tid & 127;
    const int w    = tid >> 5;         // 0..27
    const int lane = tid & 31;

    int nrows = BB - NGRP * (int)blockIdx.x;
    nrows = nrows > NGRP ? NGRP : nrows;          // 7 or 2 (block 146)
    const bool rowact = grp < nrows;
    const int b = NGRP * blockIdx.x + grp;        // valid when rowact

    const float md = p_md[0];
    const float sd = p_sd[0];
    const float th = p_th[0];
    const float hth = 0.5f * th;
    const float inv_bd = 1.0f / (float)(BB * DD);

    // Init per-feature gates (fp16 packed {0.5*a, g})
    for (int idx = tid; idx < DD; idx += NTHR) {
        const float ah = 0.5f * ac[idx];
        const float g  = sigm(tw[idx]) * sigm(ig[idx]);
        s_ag[idx] = __floats2half2_rn(ah, g);
    }
    if (tid == 0) *s_step = 0;    // no global init needed (see header)
    __syncthreads();

    // LIF state in registers (thread-private across all steps)
    float4 ir[NS4], vr[NS4];
#pragma unroll
    for (int s = 0; s < NS4; ++s) {
        ir[s] = make_float4(0.f, 0.f, 0.f, 0.f);
        vr[s] = make_float4(0.f, 0.f, 0.f, 0.f);
    }

    // ============ pass1+pass2 for timestep t: LDG x into registers, entropy,
    // mask, writes c(t) fp16 into ping-pong slot (t&1), returns warp |c| sum.
    auto compute_c = [&](int t) -> float {
        if (!rowact) return 0.0f;
        const float4* xrow4 = (const float4*)(x + ((size_t)t * BB + b) * DD);
        float4 xv[NS4];
        float S = 0.0f, W = 0.0f;
#pragma unroll
        for (int s = 0; s < NS4; ++s) {
            const int d4 = s * GSZ + gtid;
            const bool act = (s < NS4 - 1) || (gtid < TAIL4);
            if (act) {
                const float4 v = __ldg(xrow4 + d4);
                xv[s] = v;
                float e;
                e = ex2a(v.x * L2E); S += e; W += v.x * e;
                e = ex2a(v.y * L2E); S += e; W += v.y * e;
                e = ex2a(v.z * L2E); S += e; W += v.z * e;
                e = ex2a(v.w * L2E); S += e; W += v.w * e;
            }
        }
        S = warp_sum(S);
        W = warp_sum(W);
        if (lane == 0) { s_rS[w] = S; s_rW[w] = W; }
        asm volatile("bar.sync %0, %1;" :: "r"(grp + 1), "n"(GSZ) : "memory");
        S = s_rS[grp * 4 + 0] + s_rS[grp * 4 + 1] + s_rS[grp * 4 + 2] + s_rS[grp * 4 + 3];
        W = s_rW[grp * 4 + 0] + s_rW[grp * 4 + 1] + s_rW[grp * 4 + 2] + s_rW[grp * 4 + 3];
        // entropy = lnS - W/S - D*1e-8  (shift-invariant; |x|<~6 so no overflow)
        const float ent = __logf(S) - __fdividef(W, S) - (float)DD * 1e-8f;

        __half2* sc2 = s_c + ((unsigned)t & 1) * (NGRP * D4 * 2) + grp * (D4 * 2);
        float asum = 0.0f;
#pragma unroll
        for (int s = 0; s < NS4; ++s) {
            const int d4 = s * GSZ + gtid;
            const bool act = (s < NS4 - 1) || (gtid < TAIL4);
            if (act) {
                const uint4 agp = *(const uint4*)(s_ag + 4 * d4);
                const float2 ag0 = __half22float2(((const __half2*)&agp)[0]);
                const float2 ag1 = __half22float2(((const __half2*)&agp)[1]);
                const float2 ag2 = __half22float2(((const __half2*)&agp)[2]);
                const float2 ag3 = __half22float2(((const __half2*)&agp)[3]);
                float4 c = xv[s];
                // mask = 0.5 + 0.5*tanh((0.5*a)*ent)  (a pre-scaled at init)
                c.x = c.x * fmaf(0.5f, tanha(ag0.x * ent), 0.5f) * ag0.y;
                c.y = c.y * fmaf(0.5f, tanha(ag1.x * ent), 0.5f) * ag1.y;
                c.z = c.z * fmaf(0.5f, tanha(ag2.x * ent), 0.5f) * ag2.y;
                c.w = c.w * fmaf(0.5f, tanha(ag3.x * ent), 0.5f) * ag3.y;
                sc2[d4 * 2 + 0] = __floats2half2_rn(c.x, c.y);
                sc2[d4 * 2 + 1] = __floats2half2_rn(c.z, c.w);
                asum += fabsf(c.x) + fabsf(c.y) + fabsf(c.z) + fabsf(c.w);
            }
        }
        return warp_sum(asum);
    };

    // ============ block-level |c| sum -> s_rA ping-pong + sync + warp0 reduce
    auto post_asum = [&](int k, float asum) -> float {
        if (lane == 0) s_rA[((unsigned)k & 1) * 32 + w] = asum;
        __syncthreads();
        float tot = 0.0f;
        if (w == 0) {
            const float vv = (lane < (NTHR / 32)) ? s_rA[((unsigned)k & 1) * 32 + lane] : 0.0f;
            tot = warp_sum(vv);
        }
        return tot;  // valid in warp 0 only
    };

    // ============ tid0: arrive at barrier k; the last arriver reads the full
    // sum, resets the parity counter, cleans the one-late bsum slot, and
    // publishes {k+1, bs} into the parity release word.
    auto arrive = [&](int k, float tot) {
        atomicAdd(&g_bsum[k], tot);
        __threadfence();
        const unsigned pos = atomicAdd(&g_cnt2[k & 1], 1);
        if (pos == NBLK - 1) {
            const float val = atomicAdd(&g_bsum[k], 0.0f);   // all adds visible
            atomicExch(&g_cnt2[k & 1], 0u);                  // pre-release reset
            atomicExch(&g_bsum[(k + TT - 1) % TT], 0.0f);    // one-late clean
            __threadfence();
            const unsigned long long rel =
                ((unsigned long long)(unsigned)(k + 1) << 32)
                | (unsigned long long)__float_as_uint(val * inv_bd);
            atomicExch(&g_rel2[k & 1], rel);
        }
    };

    // ---------------- prologue: c(0) -> slot 0, arrive(0)
    {
        float asum = compute_c(0);
        float tot = post_asum(0, asum);
        if (tid == 0) arrive(0, tot);
    }

    for (int t = 0; t < TT; ++t) {
        // ---- pass1+2 for t+1 (independent of bs(t)) hides barrier latency
        float tot = 0.0f;
        const bool has_next = (t + 1) < TT;
        if (has_next) {
            float asum = compute_c(t + 1);
            tot = post_asum(t + 1, asum);
        } else {
            __syncthreads();
        }

        // ---- tid0: ARRIVE-FIRST at barrier t+1 (off the release(t) chain),
        //      then equality-spin on the parity-(t&1) release word for step t.
        if (tid == 0) {
            if (has_next) arrive(t + 1, tot);
            unsigned long long u;
            while ((unsigned)((u = *(volatile unsigned long long*)&g_rel2[t & 1]) >> 32)
                   != (unsigned)(t + 1)) __nanosleep(32);
            *(volatile float*)s_bsv = __uint_as_float((unsigned)u);
            __threadfence_block();
            *s_step = t + 1;                                  // publish
        }

        // ---- per-warp pickup (warps stagger straight into pass3)
        float bs;
        if (lane == 0) {
            while (*s_step < t + 1) { }
            bs = *(volatile float*)s_bsv;
        }
        bs = __shfl_sync(0xffffffffu, bs, 0);

        // ---- pass3: LIF on c(t) (fp16 ping-pong slot t&1), state in regs.
        // spike = 0.5 + 0.5*tanh((v - th)/2)   (1 MUFU)
        if (rowact) {
            const __half2* sc2 = s_c + ((unsigned)t & 1) * (NGRP * D4 * 2) + grp * (D4 * 2);
            float4* o4 = (float4*)(out + ((size_t)t * BB + b) * DD);
#pragma unroll
            for (int s = 0; s < NS4; ++s) {
                const int d4 = s * GSZ + gtid;
                const bool act = (s < NS4 - 1) || (gtid < TAIL4);
                if (act) {
                    const float2 c01 = __half22float2(sc2[d4 * 2 + 0]);
                    const float2 c23 = __half22float2(sc2[d4 * 2 + 1]);
                    float4 sp;

                    ir[s].x = sd * ir[s].x + c01.x * bs;
                    vr[s].x = md * vr[s].x + ir[s].x;
                    sp.x = fmaf(0.5f, tanha(fmaf(0.5f, vr[s].x, -hth)), 0.5f);
                    vr[s].x -= sp.x * th;

                    ir[s].y = sd * ir[s].y + c01.y * bs;
                    vr[s].y = md * vr[s].y + ir[s].y;
                    sp.y = fmaf(0.5f, tanha(fmaf(0.5f, vr[s].y, -hth)), 0.5f);
                    vr[s].y -= sp.y * th;

                    ir[s].z = sd * ir[s].z + c23.x * bs;
                    vr[s].z = md * vr[s].z + ir[s].z;
                    sp.z = fmaf(0.5f, tanha(fmaf(0.5f, vr[s].z, -hth)), 0.5f);
                    vr[s].z -= sp.z * th;

                    ir[s].w = sd * ir[s].w + c23.y * bs;
                    vr[s].w = md * vr[s].w + ir[s].w;
                    sp.w = fmaf(0.5f, tanha(fmaf(0.5f, vr[s].w, -hth)), 0.5f);
                    vr[s].w -= sp.w * th;

                    __stcs(o4 + d4, sp);
                }
            }
        }
        // smem/global reuse safety (R13 scheme + arrive-first proofs in the
        // header comment):
        // - c ping-pong: pass2(t+1) writes slot (t+1)&1, pass3(t) reads slot
        //   t&1; slot reuse at t+2 is by the same thread that read it at t.
        // - s_rS/s_rW rewritten at k+1 only after this warp's s_step poll for
        //   step k passed; step-k readers finished before post_asum(k)'s sync.
        // - s_rA ping-ponged. s_bsv/s_step monotonic within a launch.
    }
}

extern "C" void kernel_launch(void* const* d_in, const int* in_sizes, int n_in,
                              void* d_out, int out_size)
{
    (void)in_sizes; (void)n_in; (void)out_size;
    const float* x  = (const float*)d_in[0];
    const float* ac = (const float*)d_in[1];
    const float* tw = (const float*)d_in[2];
    const float* ig = (const float*)d_in[3];
    const float* md = (const float*)d_in[4];
    const float* sd = (const float*)d_in[5];
    const float* th = (const float*)d_in[6];
    float* out = (float*)d_out;

    // bytes: c ping-pong 2*NGRP*D4*2 half2 *4B = 64736
    //      + ag DD half2 *4B = 9248
    //      + rS(32)+rW(32)+rA(64)+bsv(1)+step(1) floats = 520
    constexpr size_t SMEM_BYTES =
        (size_t)(2 * NGRP * D4 * 2) * 4 + (size_t)DD * 4 + 130 * 4;  // 74,504 B

    cudaFuncSetAttribute(snn_etad_kernel,
                         cudaFuncAttributeMaxDynamicSharedMemorySize,
                         (int)SMEM_BYTES);

    snn_etad_kernel<<<NBLK, NTHR, SMEM_BYTES>>>(x, ac, tw, ig, md, sd, th, out);
}

// round 16
// speedup vs baseline: 1.0639x; 1.0639x over previous
#include <cuda_runtime.h>
#include <cuda_fp16.h>
#include <cstdint>
#include <cstddef>

// Problem constants
#define TT 20
#define BB 1024
#define DD 2312
#define D4 578            // DD / 4, exact

// Persistent kernel: 147 blocks x 896 threads, 1 block/SM (~74.5KB smem).
// Blocks 0..145 own 7 rows each; block 146 owns rows 1022..1023.
#define NBLK 147
#define NTHR 896
#define GSZ  128          // threads per row-group
#define NGRP 7            // max rows per block
#define NS4  5            // ceil(578/128) float4 slots per thread
#define TAIL4 66          // 578 - 4*128

#define L2E 1.4426950408889634f

// Grid barrier state (R13 scheme, proven fastest: single count + 64-bit
// value-carrying release word). g_rel64 = ((step+1) << 32) | float_bits(bs).
// Every block zeroes it at init BEFORE its arrive(0); the first release
// requires all arrivals, so all resets happen-before the first release ->
// replay-deterministic. g_count reset by each releaser; g_bsum slot
// (k+TT-1)%TT cleaned one-late at release k.
__device__ unsigned           g_count = 0;
__device__ float              g_bsum[TT];
__device__ unsigned long long g_rel64 = 0ull;

__device__ __forceinline__ float warp_sum(float v) {
#pragma unroll
    for (int o = 16; o > 0; o >>= 1)
        v += __shfl_xor_sync(0xffffffffu, v, o);
    return v;
}

__device__ __forceinline__ float ex2a(float x) {
    float y; asm("ex2.approx.ftz.f32 %0, %1;" : "=f"(y) : "f"(x)); return y;
}
__device__ __forceinline__ float rcpa(float x) {
    float y; asm("rcp.approx.ftz.f32 %0, %1;" : "=f"(y) : "f"(x)); return y;
}
__device__ __forceinline__ float tanha(float x) {
    float y; asm("tanh.approx.f32 %0, %1;" : "=f"(y) : "f"(x)); return y;
}
// exact-path sigmoid (2 MUFU) — used only in one-time init
__device__ __forceinline__ float sigm(float x) {
    return rcpa(1.0f + ex2a(-x * L2E));
}

__global__ void __launch_bounds__(NTHR, 1)
snn_etad_kernel(const float* __restrict__ x,
                const float* __restrict__ ac,
                const float* __restrict__ tw,
                const float* __restrict__ ig,
                const float* __restrict__ p_md,
                const float* __restrict__ p_sd,
                const float* __restrict__ p_th,
                float* __restrict__ out)
{
    extern __shared__ char smraw[];
    // c ping-pong: [2][NGRP][D4*2] half2 (fp16 compressed values)
    __half2* s_c  = (__half2*)smraw;                    // 2*7*1156 half2
    __half2* s_ag = s_c + 2 * NGRP * D4 * 2;            // DD half2 {0.5*a, g}
    float*   s_rS = (float*)(s_ag + DD);                // 32
    float*   s_rW = s_rS + 32;                          // 32
    float*   s_rA = s_rW + 32;                          // 2 x 32 ping-pong
    float*   s_bsv = s_rA + 64;                         // 1
    volatile int* s_step = (volatile int*)(s_bsv + 1);  // 1

    const int tid  = threadIdx.x;
    const int grp  = tid >> 7;         // 0..6 row-group
    const int gtid = tid & 127;
    const int w    = tid >> 5;         // 0..27
    const int lane = tid & 31;

    int nrows = BB - NGRP * (int)blockIdx.x;
    nrows = nrows > NGRP ? NGRP : nrows;          // 7 or 2 (block 146)
    const bool rowact = grp < nrows;
    const int b = NGRP * blockIdx.x + grp;        // valid when rowact

    const float md = p_md[0];
    const float sd = p_sd[0];
    const float th = p_th[0];
    const float hth = 0.5f * th;
    const float inv_bd = 1.0f / (float)(BB * DD);

    // Init per-feature gates (fp16 packed {0.5*a, g}); reset the release word
    for (int idx = tid; idx < DD; idx += NTHR) {
        const float ah = 0.5f * ac[idx];
        const float g  = sigm(tw[idx]) * sigm(ig[idx]);
        s_ag[idx] = __floats2half2_rn(ah, g);
    }
    if (tid == 0) {
        *s_step = 0;
        atomicExch(&g_rel64, 0ull);   // all resets precede the first release
    }
    __syncthreads();

    // LIF state in registers (thread-private across all steps)
    float4 ir[NS4], vr[NS4];
#pragma unroll
    for (int s = 0; s < NS4; ++s) {
        ir[s] = make_float4(0.f, 0.f, 0.f, 0.f);
        vr[s] = make_float4(0.f, 0.f, 0.f, 0.f);
    }

    // ============ pass1+pass2 for timestep t: LDG x into registers, entropy,
    // mask, writes c(t) fp16 into ping-pong slot (t&1), returns warp |c| sum.
    auto compute_c = [&](int t) -> float {
        if (!rowact) return 0.0f;
        const float4* xrow4 = (const float4*)(x + ((size_t)t * BB + b) * DD);
        float4 xv[NS4];
        float S = 0.0f, W = 0.0f;
#pragma unroll
        for (int s = 0; s < NS4; ++s) {
            const int d4 = s * GSZ + gtid;
            const bool act = (s < NS4 - 1) || (gtid < TAIL4);
            if (act) {
                const float4 v = __ldg(xrow4 + d4);
                xv[s] = v;
                float e;
                e = ex2a(v.x * L2E); S += e; W += v.x * e;
                e = ex2a(v.y * L2E); S += e; W += v.y * e;
                e = ex2a(v.z * L2E); S += e; W += v.z * e;
                e = ex2a(v.w * L2E); S += e; W += v.w * e;
            }
        }
        S = warp_sum(S);
        W = warp_sum(W);
        if (lane == 0) { s_rS[w] = S; s_rW[w] = W; }
        asm volatile("bar.sync %0, %1;" :: "r"(grp + 1), "n"(GSZ) : "memory");
        S = s_rS[grp * 4 + 0] + s_rS[grp * 4 + 1] + s_rS[grp * 4 + 2] + s_rS[grp * 4 + 3];
        W = s_rW[grp * 4 + 0] + s_rW[grp * 4 + 1] + s_rW[grp * 4 + 2] + s_rW[grp * 4 + 3];
        // entropy = lnS - W/S - D*1e-8  (shift-invariant; |x|<~6 so no overflow)
        const float ent = __logf(S) - __fdividef(W, S) - (float)DD * 1e-8f;

        __half2* sc2 = s_c + ((unsigned)t & 1) * (NGRP * D4 * 2) + grp * (D4 * 2);
        float asum = 0.0f;
#pragma unroll
        for (int s = 0; s < NS4; ++s) {
            const int d4 = s * GSZ + gtid;
            const bool act = (s < NS4 - 1) || (gtid < TAIL4);
            if (act) {
                const uint4 agp = *(const uint4*)(s_ag + 4 * d4);
                const float2 ag0 = __half22float2(((const __half2*)&agp)[0]);
                const float2 ag1 = __half22float2(((const __half2*)&agp)[1]);
                const float2 ag2 = __half22float2(((const __half2*)&agp)[2]);
                const float2 ag3 = __half22float2(((const __half2*)&agp)[3]);
                float4 c = xv[s];
                // mask = 0.5 + 0.5*tanh((0.5*a)*ent)  (a pre-scaled at init)
                c.x = c.x * fmaf(0.5f, tanha(ag0.x * ent), 0.5f) * ag0.y;
                c.y = c.y * fmaf(0.5f, tanha(ag1.x * ent), 0.5f) * ag1.y;
                c.z = c.z * fmaf(0.5f, tanha(ag2.x * ent), 0.5f) * ag2.y;
                c.w = c.w * fmaf(0.5f, tanha(ag3.x * ent), 0.5f) * ag3.y;
                sc2[d4 * 2 + 0] = __floats2half2_rn(c.x, c.y);
                sc2[d4 * 2 + 1] = __floats2half2_rn(c.z, c.w);
                asum += fabsf(c.x) + fabsf(c.y) + fabsf(c.z) + fabsf(c.w);
            }
        }
        return warp_sum(asum);
    };

    // ============ block-level |c| sum -> s_rA ping-pong + sync + warp0 reduce
    auto post_asum = [&](int k, float asum) -> float {
        if (lane == 0) s_rA[((unsigned)k & 1) * 32 + w] = asum;
        __syncthreads();
        float tot = 0.0f;
        if (w == 0) {
            const float vv = (lane < (NTHR / 32)) ? s_rA[((unsigned)k & 1) * 32 + lane] : 0.0f;
            tot = warp_sum(vv);
        }
        return tot;  // valid in warp 0 only
    };

    // ============ tid0: arrive at barrier k; the last arriver reads the full
    // sum and publishes {k+1, bs} in ONE 64-bit release word.
    auto arrive = [&](int k, float tot) {
        atomicAdd(&g_bsum[k], tot);
        __threadfence();
        const unsigned pos = atomicAdd(&g_count, 1);
        if (pos == NBLK - 1) {
            const float val = atomicAdd(&g_bsum[k], 0.0f);   // all adds visible
            atomicExch(&g_count, 0u);
            atomicExch(&g_bsum[(k + TT - 1) % TT], 0.0f);    // one-late clean
            __threadfence();
            const unsigned long long rel =
                ((unsigned long long)(unsigned)(k + 1) << 32)
                | (unsigned long long)__float_as_uint(val * inv_bd);
            atomicExch(&g_rel64, rel);
        }
    };

    // ---------------- prologue: c(0) -> slot 0, arrive(0)
    {
        float asum = compute_c(0);
        float tot = post_asum(0, asum);
        if (tid == 0) arrive(0, tot);
    }

    for (int t = 0; t < TT; ++t) {
        // ---- pass1+2 for t+1 (independent of bs(t)) hides barrier latency
        float tot = 0.0f;
        const bool has_next = (t + 1) < TT;
        if (has_next) {
            float asum = compute_c(t + 1);
            tot = post_asum(t + 1, asum);
        } else {
            __syncthreads();
        }

        // ---- tid0: spin on the single release word until step t+1 appears
        //      (bs rides in the low 32 bits), then arrive(t+1) IMMEDIATELY
        //      (still after consume -> single-counter invariant holds), then
        //      publish bs to smem. Identical protocol to the 112.0us kernel;
        //      only the publish/arrive order is swapped to shave the release
        //      chain.
        if (tid == 0) {
            unsigned long long u;
            while ((unsigned)((u = *(volatile unsigned long long*)&g_rel64) >> 32)
                   < (unsigned)(t + 1)) __nanosleep(32);
            if (has_next) arrive(t + 1, tot);
            *(volatile float*)s_bsv = __uint_as_float((unsigned)u);
            __threadfence_block();
            *s_step = t + 1;                                  // publish
        }

        // ---- per-warp pickup (warps stagger straight into pass3)
        float bs;
        if (lane == 0) {
            while (*s_step < t + 1) { }
            bs = *(volatile float*)s_bsv;
        }
        bs = __shfl_sync(0xffffffffu, bs, 0);

        // ---- pass3: LIF on c(t) (fp16 ping-pong slot t&1), state in regs.
        // spike = 0.5 + 0.5*tanh((v - th)/2)   (1 MUFU)
        if (rowact) {
            const __half2* sc2 = s_c + ((unsigned)t & 1) * (NGRP * D4 * 2) + grp * (D4 * 2);
            float4* o4 = (float4*)(out + ((size_t)t * BB + b) * DD);
#pragma unroll
            for (int s = 0; s < NS4; ++s) {
                const int d4 = s * GSZ + gtid;
                const bool act = (s < NS4 - 1) || (gtid < TAIL4);
                if (act) {
                    const float2 c01 = __half22float2(sc2[d4 * 2 + 0]);
                    const float2 c23 = __half22float2(sc2[d4 * 2 + 1]);
                    float4 sp;

                    ir[s].x = sd * ir[s].x + c01.x * bs;
                    vr[s].x = md * vr[s].x + ir[s].x;
                    sp.x = fmaf(0.5f, tanha(fmaf(0.5f, vr[s].x, -hth)), 0.5f);
                    vr[s].x -= sp.x * th;

                    ir[s].y = sd * ir[s].y + c01.y * bs;
                    vr[s].y = md * vr[s].y + ir[s].y;
                    sp.y = fmaf(0.5f, tanha(fmaf(0.5f, vr[s].y, -hth)), 0.5f);
                    vr[s].y -= sp.y * th;

                    ir[s].z = sd * ir[s].z + c23.x * bs;
                    vr[s].z = md * vr[s].z + ir[s].z;
                    sp.z = fmaf(0.5f, tanha(fmaf(0.5f, vr[s].z, -hth)), 0.5f);
                    vr[s].z -= sp.z * th;

                    ir[s].w = sd * ir[s].w + c23.y * bs;
                    vr[s].w = md * vr[s].w + ir[s].w;
                    sp.w = fmaf(0.5f, tanha(fmaf(0.5f, vr[s].w, -hth)), 0.5f);
                    vr[s].w -= sp.w * th;

                    __stcs(o4 + d4, sp);
                }
            }
        }
        // smem/global reuse safety (identical to the proven R13 scheme):
        // - c ping-pong: pass2(t+1) writes slot (t+1)&1, pass3(t) reads slot
        //   t&1; slot reuse at t+2 is by the same thread that read it at t.
        // - s_rS/s_rW rewritten at k+1 only after this warp's s_step poll for
        //   step k passed; step-k readers finished before post_asum(k)'s sync.
        // - s_rA ping-ponged. s_bsv/s_step monotonic within a launch.
        // - g_rel64 high word increases monotonically 1..TT within a launch;
        //   zeroed by all blocks at the start of the next launch.
    }
}

extern "C" void kernel_launch(void* const* d_in, const int* in_sizes, int n_in,
                              void* d_out, int out_size)
{
    (void)in_sizes; (void)n_in; (void)out_size;
    const float* x  = (const float*)d_in[0];
    const float* ac = (const float*)d_in[1];
    const float* tw = (const float*)d_in[2];
    const float* ig = (const float*)d_in[3];
    const float* md = (const float*)d_in[4];
    const float* sd = (const float*)d_in[5];
    const float* th = (const float*)d_in[6];
    float* out = (float*)d_out;

    // bytes: c ping-pong 2*NGRP*D4*2 half2 *4B = 64736
    //      + ag DD half2 *4B = 9248
    //      + rS(32)+rW(32)+rA(64)+bsv(1)+step(1) floats = 520
    constexpr size_t SMEM_BYTES =
        (size_t)(2 * NGRP * D4 * 2) * 4 + (size_t)DD * 4 + 130 * 4;  // 74,504 B

    cudaFuncSetAttribute(snn_etad_kernel,
                         cudaFuncAttributeMaxDynamicSharedMemorySize,
                         (int)SMEM_BYTES);

    snn_etad_kernel<<<NBLK, NTHR, SMEM_BYTES>>>(x, ac, tw, ig, md, sd, th, out);
}

// round 17
// speedup vs baseline: 1.2886x; 1.2112x over previous
#include <cuda_runtime.h>
#include <cuda_fp16.h>
#include <cstdint>
#include <cstddef>

// Problem constants
#define TT 20
#define BB 1024
#define DD 2312
#define D4 578            // DD / 4, exact

// Persistent kernel: 147 blocks x 896 threads, 1 block/SM (~74.5KB smem).
// Blocks 0..145 own 7 rows each; block 146 owns rows 1022..1023.
#define NBLK 147
#define NTHR 896
#define GSZ  128          // threads per row-group
#define NGRP 7            // max rows per block
#define NS4  5            // ceil(578/128) float4 slots per thread
#define TAIL4 66          // 578 - 4*128

#define L2E 1.4426950408889634f

// Grid barrier state (R13 scheme: single count + 64-bit value-carrying
// release word). g_rel64 = ((step+1) << 32) | float_bits(bs). Every block
// zeroes it at init BEFORE its arrive(0); the first release requires all
// arrivals, so all resets happen-before the first release ->
// replay-deterministic. g_count reset by each releaser; g_bsum slot
// (k+TT-1)%TT cleaned one-late at release k.
__device__ unsigned           g_count = 0;
__device__ float              g_bsum[TT];
__device__ unsigned long long g_rel64 = 0ull;

__device__ __forceinline__ float warp_sum(float v) {
#pragma unroll
    for (int o = 16; o > 0; o >>= 1)
        v += __shfl_xor_sync(0xffffffffu, v, o);
    return v;
}

__device__ __forceinline__ float ex2a(float x) {
    float y; asm("ex2.approx.ftz.f32 %0, %1;" : "=f"(y) : "f"(x)); return y;
}
__device__ __forceinline__ float rcpa(float x) {
    float y; asm("rcp.approx.ftz.f32 %0, %1;" : "=f"(y) : "f"(x)); return y;
}
__device__ __forceinline__ float tanha(float x) {
    float y; asm("tanh.approx.f32 %0, %1;" : "=f"(y) : "f"(x)); return y;
}
// exact-path sigmoid (2 MUFU) — used only in one-time init
__device__ __forceinline__ float sigm(float x) {
    return rcpa(1.0f + ex2a(-x * L2E));
}

__global__ void __launch_bounds__(NTHR, 1)
snn_etad_kernel(const float* __restrict__ x,
                const float* __restrict__ ac,
                const float* __restrict__ tw,
                const float* __restrict__ ig,
                const float* __restrict__ p_md,
                const float* __restrict__ p_sd,
                const float* __restrict__ p_th,
                float* __restrict__ out)
{
    extern __shared__ char smraw[];
    // c ping-pong: [2][NGRP][D4*2] half2 (fp16 compressed values)
    __half2* s_c  = (__half2*)smraw;                    // 2*7*1156 half2
    __half2* s_ag = s_c + 2 * NGRP * D4 * 2;            // DD half2 {0.5*a, g}
    float*   s_rS = (float*)(s_ag + DD);                // 32
    float*   s_rW = s_rS + 32;                          // 32
    float*   s_rA = s_rW + 32;                          // 2 x 32 ping-pong
    float*   s_bsv = s_rA + 64;                         // 1
    volatile int* s_step = (volatile int*)(s_bsv + 1);  // 1

    const int tid  = threadIdx.x;
    const int grp  = tid >> 7;         // 0..6 row-group
    const int gtid = tid & 127;
    const int w    = tid >> 5;         // 0..27
    const int lane = tid & 31;

    int nrows = BB - NGRP * (int)blockIdx.x;
    nrows = nrows > NGRP ? NGRP : nrows;          // 7 or 2 (block 146)
    const bool rowact = grp < nrows;
    const int b = NGRP * blockIdx.x + grp;        // valid when rowact

    const float md = p_md[0];
    const float sd = p_sd[0];
    const float th = p_th[0];
    const float hth = 0.5f * th;
    const float inv_bd = 1.0f / (float)(BB * DD);

    // Init per-feature gates (fp16 packed {0.5*a, g}); reset the release word
    for (int idx = tid; idx < DD; idx += NTHR) {
        const float ah = 0.5f * ac[idx];
        const float g  = sigm(tw[idx]) * sigm(ig[idx]);
        s_ag[idx] = __floats2half2_rn(ah, g);
    }
    if (tid == 0) {
        *s_step = 0;
        atomicExch(&g_rel64, 0ull);   // all resets precede the first release
    }
    __syncthreads();

    // LIF state in registers (thread-private across all steps)
    float4 ir[NS4], vr[NS4];
#pragma unroll
    for (int s = 0; s < NS4; ++s) {
        ir[s] = make_float4(0.f, 0.f, 0.f, 0.f);
        vr[s] = make_float4(0.f, 0.f, 0.f, 0.f);
    }

    // ============ pass1+pass2 for timestep t: LDG x into registers, entropy,
    // mask, writes c(t) fp16 into ping-pong slot (t&1), returns warp |c| sum.
    auto compute_c = [&](int t) -> float {
        if (!rowact) return 0.0f;
        const float4* xrow4 = (const float4*)(x + ((size_t)t * BB + b) * DD);
        float4 xv[NS4];
        float S = 0.0f, W = 0.0f;
#pragma unroll
        for (int s = 0; s < NS4; ++s) {
            const int d4 = s * GSZ + gtid;
            const bool act = (s < NS4 - 1) || (gtid < TAIL4);
            if (act) {
                const float4 v = __ldg(xrow4 + d4);
                xv[s] = v;
                float e;
                e = ex2a(v.x * L2E); S += e; W += v.x * e;
                e = ex2a(v.y * L2E); S += e; W += v.y * e;
                e = ex2a(v.z * L2E); S += e; W += v.z * e;
                e = ex2a(v.w * L2E); S += e; W += v.w * e;
            }
        }
        S = warp_sum(S);
        W = warp_sum(W);
        if (lane == 0) { s_rS[w] = S; s_rW[w] = W; }
        asm volatile("bar.sync %0, %1;" :: "r"(grp + 1), "n"(GSZ) : "memory");
        S = s_rS[grp * 4 + 0] + s_rS[grp * 4 + 1] + s_rS[grp * 4 + 2] + s_rS[grp * 4 + 3];
        W = s_rW[grp * 4 + 0] + s_rW[grp * 4 + 1] + s_rW[grp * 4 + 2] + s_rW[grp * 4 + 3];
        // entropy = lnS - W/S - D*1e-8  (shift-invariant; |x|<~6 so no overflow)
        const float ent = __logf(S) - __fdividef(W, S) - (float)DD * 1e-8f;

        __half2* sc2 = s_c + ((unsigned)t & 1) * (NGRP * D4 * 2) + grp * (D4 * 2);
        float asum = 0.0f;
#pragma unroll
        for (int s = 0; s < NS4; ++s) {
            const int d4 = s * GSZ + gtid;
            const bool act = (s < NS4 - 1) || (gtid < TAIL4);
            if (act) {
                const uint4 agp = *(const uint4*)(s_ag + 4 * d4);
                const float2 ag0 = __half22float2(((const __half2*)&agp)[0]);
                const float2 ag1 = __half22float2(((const __half2*)&agp)[1]);
                const float2 ag2 = __half22float2(((const __half2*)&agp)[2]);
                const float2 ag3 = __half22float2(((const __half2*)&agp)[3]);
                float4 c = xv[s];
                // mask = 0.5 + 0.5*tanh((0.5*a)*ent)  (a pre-scaled at init)
                c.x = c.x * fmaf(0.5f, tanha(ag0.x * ent), 0.5f) * ag0.y;
                c.y = c.y * fmaf(0.5f, tanha(ag1.x * ent), 0.5f) * ag1.y;
                c.z = c.z * fmaf(0.5f, tanha(ag2.x * ent), 0.5f) * ag2.y;
                c.w = c.w * fmaf(0.5f, tanha(ag3.x * ent), 0.5f) * ag3.y;
                sc2[d4 * 2 + 0] = __floats2half2_rn(c.x, c.y);
                sc2[d4 * 2 + 1] = __floats2half2_rn(c.z, c.w);
                asum += fabsf(c.x) + fabsf(c.y) + fabsf(c.z) + fabsf(c.w);
            }
        }
        return warp_sum(asum);
    };

    // ============ block-level |c| sum -> s_rA ping-pong + sync + warp0 reduce
    auto post_asum = [&](int k, float asum) -> float {
        if (lane == 0) s_rA[((unsigned)k & 1) * 32 + w] = asum;
        __syncthreads();
        float tot = 0.0f;
        if (w == 0) {
            const float vv = (lane < (NTHR / 32)) ? s_rA[((unsigned)k & 1) * 32 + lane] : 0.0f;
            tot = warp_sum(vv);
        }
        return tot;  // valid in warp 0 only
    };

    // ============ tid0: arrive at barrier k; the last arriver reads the full
    // sum and publishes {k+1, bs} in ONE 64-bit release word.
    auto arrive = [&](int k, float tot) {
        atomicAdd(&g_bsum[k], tot);
        __threadfence();
        const unsigned pos = atomicAdd(&g_count, 1);
        if (pos == NBLK - 1) {
            const float val = atomicAdd(&g_bsum[k], 0.0f);   // all adds visible
            atomicExch(&g_count, 0u);
            atomicExch(&g_bsum[(k + TT - 1) % TT], 0.0f);    // one-late clean
            __threadfence();
            const unsigned long long rel =
                ((unsigned long long)(unsigned)(k + 1) << 32)
                | (unsigned long long)__float_as_uint(val * inv_bd);
            atomicExch(&g_rel64, rel);
        }
    };

    // ---------------- prologue: c(0) -> slot 0, arrive(0)
    {
        float asum = compute_c(0);
        float tot = post_asum(0, asum);
        if (tid == 0) arrive(0, tot);
    }

    for (int t = 0; t < TT; ++t) {
        // ---- pass1+2 for t+1 (independent of bs(t)) hides barrier latency
        float tot = 0.0f;
        const bool has_next = (t + 1) < TT;
        if (has_next) {
            float asum = compute_c(t + 1);
            tot = post_asum(t + 1, asum);
        } else {
            __syncthreads();
        }

        // ---- tid0: spin on the single release word until step t+1 appears;
        //      bs rides in the low 32 bits (no extra fence/atomic read).
        //      Then arrive(t+1) (proven order: consume, publish, arrive).
        if (tid == 0) {
            unsigned long long u;
            while ((unsigned)((u = *(volatile unsigned long long*)&g_rel64) >> 32)
                   < (unsigned)(t + 1)) __nanosleep(32);
            *(volatile float*)s_bsv = __uint_as_float((unsigned)u);
            __threadfence_block();
            *s_step = t + 1;                                  // publish
            if (has_next) arrive(t + 1, tot);
        }

        // ---- per-warp pickup (warps stagger straight into pass3)
        float bs;
        if (lane == 0) {
            while (*s_step < t + 1) { }
            bs = *(volatile float*)s_bsv;
        }
        bs = __shfl_sync(0xffffffffu, bs, 0);

        // ---- pass3: LIF on c(t) (fp16 ping-pong slot t&1), state in regs.
        // spike = 0.5 + 0.5*tanh((v - th)/2)   (1 MUFU)
        if (rowact) {
            const __half2* sc2 = s_c + ((unsigned)t & 1) * (NGRP * D4 * 2) + grp * (D4 * 2);
            float4* o4 = (float4*)(out + ((size_t)t * BB + b) * DD);
#pragma unroll
            for (int s = 0; s < NS4; ++s) {
                const int d4 = s * GSZ + gtid;
                const bool act = (s < NS4 - 1) || (gtid < TAIL4);
                if (act) {
                    const float2 c01 = __half22float2(sc2[d4 * 2 + 0]);
                    const float2 c23 = __half22float2(sc2[d4 * 2 + 1]);
                    float4 sp;

                    ir[s].x = sd * ir[s].x + c01.x * bs;
                    vr[s].x = md * vr[s].x + ir[s].x;
                    sp.x = fmaf(0.5f, tanha(fmaf(0.5f, vr[s].x, -hth)), 0.5f);
                    vr[s].x -= sp.x * th;

                    ir[s].y = sd * ir[s].y + c01.y * bs;
                    vr[s].y = md * vr[s].y + ir[s].y;
                    sp.y = fmaf(0.5f, tanha(fmaf(0.5f, vr[s].y, -hth)), 0.5f);
                    vr[s].y -= sp.y * th;

                    ir[s].z = sd * ir[s].z + c23.x * bs;
                    vr[s].z = md * vr[s].z + ir[s].z;
                    sp.z = fmaf(0.5f, tanha(fmaf(0.5f, vr[s].z, -hth)), 0.5f);
                    vr[s].z -= sp.z * th;

                    ir[s].w = sd * ir[s].w + c23.y * bs;
                    vr[s].w = md * vr[s].w + ir[s].w;
                    sp.w = fmaf(0.5f, tanha(fmaf(0.5f, vr[s].w, -hth)), 0.5f);
                    vr[s].w -= sp.w * th;

                    __stcs(o4 + d4, sp);
                }
            }
        }
        // smem/global reuse safety (identical to the proven R13 scheme):
        // - c ping-pong: pass2(t+1) writes slot (t+1)&1, pass3(t) reads slot
        //   t&1; slot reuse at t+2 is by the same thread that read it at t.
        // - s_rS/s_rW rewritten at k+1 only after this warp's s_step poll for
        //   step k passed; step-k readers finished before post_asum(k)'s sync.
        // - s_rA ping-ponged. s_bsv/s_step monotonic within a launch.
        // - g_rel64 high word increases monotonically 1..TT within a launch;
        //   zeroed by all blocks at the start of the next launch.
    }
}

extern "C" void kernel_launch(void* const* d_in, const int* in_sizes, int n_in,
                              void* d_out, int out_size)
{
    (void)in_sizes; (void)n_in; (void)out_size;
    const float* x  = (const float*)d_in[0];
    const float* ac = (const float*)d_in[1];
    const float* tw = (const float*)d_in[2];
    const float* ig = (const float*)d_in[3];
    const float* md = (const float*)d_in[4];
    const float* sd = (const float*)d_in[5];
    const float* th = (const float*)d_in[6];
    float* out = (float*)d_out;

    // bytes: c ping-pong 2*NGRP*D4*2 half2 *4B = 64736
    //      + ag DD half2 *4B = 9248
    //      + rS(32)+rW(32)+rA(64)+bsv(1)+step(1) floats = 520
    constexpr size_t SMEM_BYTES =
        (size_t)(2 * NGRP * D4 * 2) * 4 + (size_t)DD * 4 + 130 * 4;  // 74,504 B

    cudaFuncSetAttribute(snn_etad_kernel,
                         cudaFuncAttributeMaxDynamicSharedMemorySize,
                         (int)SMEM_BYTES);

    snn_etad_kernel<<<NBLK, NTHR, SMEM_BYTES>>>(x, ac, tw, ig, md, sd, th, out);
}